// round 1
// baseline (speedup 1.0000x reference)
#include <cuda_runtime.h>
#include <cuda_bf16.h>
#include <math.h>

#define BATCH 8
#define CDIM  512
#define INNER 256
#define QKV   768
#define HEADS 8
#define DH    32
#define HH    96
#define WW    96
#define HW    9216   // 96*96

// ---------------- scratch (static device globals; no cudaMalloc allowed) ----
__device__ float g_xn  [(size_t)BATCH * CDIM  * HW];  // normalized input
__device__ float g_qkv1[(size_t)BATCH * QKV   * HW];  // after 1x1
__device__ float g_qkv2[(size_t)BATCH * QKV   * HW];  // after dwconv3
__device__ float g_attn[(size_t)BATCH * INNER * HW];  // after attention + silu
__device__ float g_z   [(size_t)BATCH * CDIM  * HW];  // after out conv1x1
__device__ float g_wqkv[(size_t)QKV * CDIM];          // concat of q/k/v 1x1 weights
__device__ float g_kmax [BATCH * INNER];
__device__ float g_krsum[BATCH * INNER];
__device__ float g_ctx  [BATCH * HEADS * DH * DH];

// ---------------- weight concat -------------------------------------------
__global__ void concat_w_kernel(const float* __restrict__ qw,
                                const float* __restrict__ kw,
                                const float* __restrict__ vw) {
    int i = blockIdx.x * blockDim.x + threadIdx.x;  // 0 .. 256*512-1
    g_wqkv[i]               = qw[i];
    g_wqkv[i + INNER*CDIM]  = kw[i];
    g_wqkv[i + 2*INNER*CDIM]= vw[i];
}

// ---------------- channel layernorm (gamma only, biased var) ---------------
__device__ __forceinline__ void chan_ln_body(const float* __restrict__ x,
                                             const float* __restrict__ g,
                                             float* __restrict__ y) {
    int pos = blockIdx.x * blockDim.x + threadIdx.x;  // 0 .. BATCH*HW-1
    int b = pos / HW;
    int hw = pos - b * HW;
    const float* xb = x + (size_t)b * CDIM * HW + hw;
    float* yb       = y + (size_t)b * CDIM * HW + hw;
    float s = 0.f, s2 = 0.f;
    #pragma unroll 8
    for (int c = 0; c < CDIM; c++) {
        float v = xb[(size_t)c * HW];
        s += v; s2 += v * v;
    }
    const float invC = 1.0f / CDIM;
    float mean = s * invC;
    float var  = s2 * invC - mean * mean;
    float r = rsqrtf(var + 1e-5f);
    #pragma unroll 8
    for (int c = 0; c < CDIM; c++) {
        yb[(size_t)c * HW] = (xb[(size_t)c * HW] - mean) * r * g[c];
    }
}

__global__ void ln_in_kernel(const float* __restrict__ fmap,
                             const float* __restrict__ gamma) {
    chan_ln_body(fmap, gamma, g_xn);
}
__global__ void ln_out_kernel(const float* __restrict__ gamma,
                              float* __restrict__ out) {
    chan_ln_body(g_z, gamma, out);
}

// ---------------- fp32 tiled SGEMM: Y[b] = A[M,K] @ X[b][K,N] --------------
// BM=BN=128, BK=16, 256 threads, 8x8 per thread. M,K multiples of tile; N=9216.
__device__ __forceinline__ void sgemm_body(const float* __restrict__ A,
                                           const float* __restrict__ X,
                                           float* __restrict__ Y,
                                           int M, int K) {
    const int N = HW;
    __shared__ float As[16][128];
    __shared__ float Bs[16][128];
    int b = blockIdx.z;
    const float* Xb = X + (size_t)b * K * N;
    float* Yb       = Y + (size_t)b * M * N;
    int tm0 = blockIdx.y * 128;
    int tn0 = blockIdx.x * 128;
    int t = threadIdx.x;  // 0..255
    int arow = t >> 2;           // 0..63
    int acol = (t & 3) * 4;      // 0,4,8,12
    int brow = t >> 5;           // 0..7
    int bcol = (t & 31) * 4;     // 0..124
    int ty = t >> 4, tx = t & 15;
    float acc[8][8];
    #pragma unroll
    for (int i = 0; i < 8; i++)
        #pragma unroll
        for (int j = 0; j < 8; j++) acc[i][j] = 0.f;

    for (int k0 = 0; k0 < K; k0 += 16) {
        #pragma unroll
        for (int i = 0; i < 2; i++) {
            int r = arow + i * 64;
            float4 av = *(const float4*)(A + (size_t)(tm0 + r) * K + k0 + acol);
            As[acol + 0][r] = av.x;
            As[acol + 1][r] = av.y;
            As[acol + 2][r] = av.z;
            As[acol + 3][r] = av.w;
        }
        #pragma unroll
        for (int i = 0; i < 2; i++) {
            int r = brow + i * 8;
            float4 bv = *(const float4*)(Xb + (size_t)(k0 + r) * N + tn0 + bcol);
            *(float4*)(&Bs[r][bcol]) = bv;
        }
        __syncthreads();
        #pragma unroll
        for (int kk = 0; kk < 16; kk++) {
            float ra[8], rb[8];
            #pragma unroll
            for (int i = 0; i < 8; i++) ra[i] = As[kk][ty * 8 + i];
            #pragma unroll
            for (int j = 0; j < 8; j++) rb[j] = Bs[kk][tx * 8 + j];
            #pragma unroll
            for (int i = 0; i < 8; i++)
                #pragma unroll
                for (int j = 0; j < 8; j++)
                    acc[i][j] += ra[i] * rb[j];
        }
        __syncthreads();
    }
    #pragma unroll
    for (int i = 0; i < 8; i++) {
        int m = tm0 + ty * 8 + i;
        float* yr = Yb + (size_t)m * N + tn0 + tx * 8;
        *(float4*)(yr)     = make_float4(acc[i][0], acc[i][1], acc[i][2], acc[i][3]);
        *(float4*)(yr + 4) = make_float4(acc[i][4], acc[i][5], acc[i][6], acc[i][7]);
    }
}

__global__ void __launch_bounds__(256) sgemm_qkv_kernel() {
    sgemm_body(g_wqkv, g_xn, g_qkv1, QKV, CDIM);
}
__global__ void __launch_bounds__(256) sgemm_out_kernel(const float* __restrict__ out_w) {
    sgemm_body(out_w, g_attn, g_z, CDIM, INNER);
}

// ---------------- depthwise 3x3 (SAME, zero pad) ---------------------------
__global__ void dwconv3_kernel(const float* __restrict__ qwd,
                               const float* __restrict__ kwd,
                               const float* __restrict__ vwd) {
    long idx = (long)blockIdx.x * blockDim.x + threadIdx.x;  // BATCH*QKV*HW
    int w = idx % WW;
    long tt = idx / WW;
    int h = tt % HH; tt /= HH;
    int c = tt % QKV;
    int b = tt / QKV;
    const float* wp = (c < 256) ? (qwd + c * 9)
                    : (c < 512) ? (kwd + (c - 256) * 9)
                                : (vwd + (c - 512) * 9);
    const float* ip = g_qkv1 + ((size_t)b * QKV + c) * HW;
    float s = 0.f;
    #pragma unroll
    for (int dy = -1; dy <= 1; dy++) {
        int hh = h + dy;
        if (hh < 0 || hh >= HH) continue;
        #pragma unroll
        for (int dx = -1; dx <= 1; dx++) {
            int ww2 = w + dx;
            if (ww2 < 0 || ww2 >= WW) continue;
            s += wp[(dy + 1) * 3 + (dx + 1)] * ip[hh * WW + ww2];
        }
    }
    g_qkv2[idx] = s;
}

// ---------------- k softmax stats (max & 1/sum over spatial) ---------------
__global__ void kstats_kernel() {
    int bc = blockIdx.x;            // 0 .. BATCH*INNER-1
    int b = bc / INNER, c = bc % INNER;
    const float* kp = g_qkv2 + ((size_t)b * QKV + INNER + c) * HW;
    int t = threadIdx.x;
    __shared__ float sm[256];
    float m = -1e30f;
    for (int i = t; i < HW; i += 256) m = fmaxf(m, kp[i]);
    sm[t] = m; __syncthreads();
    for (int s = 128; s > 0; s >>= 1) { if (t < s) sm[t] = fmaxf(sm[t], sm[t + s]); __syncthreads(); }
    m = sm[0];
    __syncthreads();
    float sum = 0.f;
    for (int i = t; i < HW; i += 256) sum += __expf(kp[i] - m);
    sm[t] = sum; __syncthreads();
    for (int s = 128; s > 0; s >>= 1) { if (t < s) sm[t] += sm[t + s]; __syncthreads(); }
    if (t == 0) { g_kmax[bc] = m; g_krsum[bc] = 1.0f / sm[0]; }
}

// ---------------- context = softmax_k^T @ v  (32x32 per (b,h)) -------------
__global__ void context_kernel() {
    int b = blockIdx.x / HEADS, h = blockIdx.x % HEADS;
    const float* kp = g_qkv2 + ((size_t)b * QKV + INNER + h * DH) * HW;
    const float* vp = g_qkv2 + ((size_t)b * QKV + 2 * INNER + h * DH) * HW;
    const float* km = g_kmax  + b * INNER + h * DH;
    const float* kr = g_krsum + b * INNER + h * DH;
    __shared__ float sk[DH][33];
    __shared__ float sv[DH][33];
    int t = threadIdx.x;           // 256
    int e = t & 31;
    int d0 = (t >> 5) * 4;         // 8 groups * 4 = 32 d's
    float acc0 = 0.f, acc1 = 0.f, acc2 = 0.f, acc3 = 0.f;
    for (int n0 = 0; n0 < HW; n0 += 32) {
        #pragma unroll
        for (int i = 0; i < 4; i++) {
            int idx = t + i * 256;
            int d = idx >> 5, nn = idx & 31;
            float kv = kp[(size_t)d * HW + n0 + nn];
            sk[d][nn] = __expf(kv - km[d]) * kr[d];
            sv[d][nn] = vp[(size_t)d * HW + n0 + nn];
        }
        __syncthreads();
        #pragma unroll
        for (int nn = 0; nn < 32; nn++) {
            float vv = sv[e][nn];
            acc0 += sk[d0 + 0][nn] * vv;
            acc1 += sk[d0 + 1][nn] * vv;
            acc2 += sk[d0 + 2][nn] * vv;
            acc3 += sk[d0 + 3][nn] * vv;
        }
        __syncthreads();
    }
    float* cp = g_ctx + (size_t)(b * HEADS + h) * DH * DH;
    cp[(d0 + 0) * DH + e] = acc0;
    cp[(d0 + 1) * DH + e] = acc1;
    cp[(d0 + 2) * DH + e] = acc2;
    cp[(d0 + 3) * DH + e] = acc3;
}

// ---------------- q softmax (over dh) @ context + silu ---------------------
__global__ void qattn_kernel() {
    int bh = blockIdx.y;
    int b = bh / HEADS, h = bh % HEADS;
    int n = blockIdx.x * 256 + threadIdx.x;
    __shared__ float sctx[DH][DH];
    for (int i = threadIdx.x; i < DH * DH; i += 256)
        sctx[i / DH][i % DH] = g_ctx[(size_t)bh * DH * DH + i];
    __syncthreads();
    const float* qp = g_qkv2 + ((size_t)b * QKV + h * DH) * HW + n;
    float qv[DH];
    float m = -1e30f;
    #pragma unroll
    for (int d = 0; d < DH; d++) { qv[d] = qp[(size_t)d * HW]; m = fmaxf(m, qv[d]); }
    float sum = 0.f;
    #pragma unroll
    for (int d = 0; d < DH; d++) { qv[d] = __expf(qv[d] - m); sum += qv[d]; }
    float sc = 0.17677669529663688f / sum;  // (1/sqrt(32)) / sum
    #pragma unroll
    for (int d = 0; d < DH; d++) qv[d] *= sc;
    float* op = g_attn + ((size_t)b * INNER + h * DH) * HW + n;
    #pragma unroll
    for (int e = 0; e < DH; e++) {
        float o = 0.f;
        #pragma unroll
        for (int d = 0; d < DH; d++) o += qv[d] * sctx[d][e];
        o = o / (1.0f + __expf(-o));   // silu
        op[(size_t)e * HW] = o;
    }
}

// ---------------- launch ----------------------------------------------------
extern "C" void kernel_launch(void* const* d_in, const int* in_sizes, int n_in,
                              void* d_out, int out_size) {
    const float* fmap      = (const float*)d_in[0];
    const float* norm_g    = (const float*)d_in[1];
    const float* q_w1      = (const float*)d_in[2];
    const float* q_wd      = (const float*)d_in[3];
    const float* k_w1      = (const float*)d_in[4];
    const float* k_wd      = (const float*)d_in[5];
    const float* v_w1      = (const float*)d_in[6];
    const float* v_wd      = (const float*)d_in[7];
    const float* out_w     = (const float*)d_in[8];
    const float* out_norm_g= (const float*)d_in[9];
    float* out = (float*)d_out;

    concat_w_kernel<<<(INNER * CDIM) / 256, 256>>>(q_w1, k_w1, v_w1);
    ln_in_kernel<<<(BATCH * HW) / 256, 256>>>(fmap, norm_g);
    sgemm_qkv_kernel<<<dim3(HW / 128, QKV / 128, BATCH), 256>>>();
    {
        long total = (long)BATCH * QKV * HW;
        dwconv3_kernel<<<(unsigned)(total / 256), 256>>>(q_wd, k_wd, v_wd);
    }
    kstats_kernel<<<BATCH * INNER, 256>>>();
    context_kernel<<<BATCH * HEADS, 256>>>();
    qattn_kernel<<<dim3(HW / 256, BATCH * HEADS), 256>>>();
    sgemm_out_kernel<<<dim3(HW / 128, CDIM / 128, BATCH), 256>>>(out_w);
    ln_out_kernel<<<(BATCH * HW) / 256, 256>>>(out_norm_g, out);
}

// round 3
// speedup vs baseline: 2.0267x; 2.0267x over previous
#include <cuda_runtime.h>
#include <cuda_bf16.h>
#include <math.h>
#include <stdint.h>

#define BATCH 8
#define CDIM  512
#define INNER 256
#define QKV   768
#define HEADS 8
#define DH    32
#define HH    96
#define WW    96
#define HW    9216   // 96*96

// ---------------- scratch (static device globals) ---------------------------
__device__ __nv_bfloat16 g_xh [(size_t)BATCH * CDIM  * HW];  // LN(x) hi
__device__ __nv_bfloat16 g_xl [(size_t)BATCH * CDIM  * HW];  // LN(x) lo
__device__ float g_qkv1[(size_t)BATCH * QKV   * HW];          // after 1x1
__device__ float g_qkv2[(size_t)BATCH * QKV   * HW];          // after dwconv3
__device__ __nv_bfloat16 g_ah [(size_t)BATCH * INNER * HW];   // attn+silu hi
__device__ __nv_bfloat16 g_al [(size_t)BATCH * INNER * HW];   // attn+silu lo
__device__ float g_z   [(size_t)BATCH * CDIM  * HW];          // after out conv1x1
__device__ __nv_bfloat16 g_wh [(size_t)QKV * CDIM];           // qkv weights hi
__device__ __nv_bfloat16 g_wl [(size_t)QKV * CDIM];           // qkv weights lo
__device__ __nv_bfloat16 g_owh[(size_t)CDIM * INNER];         // out weights hi
__device__ __nv_bfloat16 g_owl[(size_t)CDIM * INNER];         // out weights lo
__device__ float g_kmax [BATCH * INNER];
__device__ float g_krsum[BATCH * INNER];
__device__ float g_ctx  [BATCH * HEADS * DH * DH];
__device__ float g_ctxp [(size_t)9 * BATCH * HEADS * DH * DH];

__device__ __forceinline__ void split_bf16(float v, __nv_bfloat16& h, __nv_bfloat16& l) {
    h = __float2bfloat16(v);
    l = __float2bfloat16(v - __bfloat162float(h));
}

// ---------------- weight conversion ----------------------------------------
__global__ void convert_qkvw_kernel(const float* __restrict__ qw,
                                    const float* __restrict__ kw,
                                    const float* __restrict__ vw) {
    int i = blockIdx.x * blockDim.x + threadIdx.x;  // 0 .. INNER*CDIM-1
    split_bf16(qw[i], g_wh[i], g_wl[i]);
    split_bf16(kw[i], g_wh[i + INNER*CDIM], g_wl[i + INNER*CDIM]);
    split_bf16(vw[i], g_wh[i + 2*INNER*CDIM], g_wl[i + 2*INNER*CDIM]);
}
__global__ void convert_outw_kernel(const float* __restrict__ ow) {
    int i = blockIdx.x * blockDim.x + threadIdx.x;  // 0 .. CDIM*INNER-1
    split_bf16(ow[i], g_owh[i], g_owl[i]);
}

// ---------------- input channel layernorm -> split bf16 planes -------------
__global__ void ln_in_kernel(const float* __restrict__ x,
                             const float* __restrict__ g) {
    int pos = blockIdx.x * blockDim.x + threadIdx.x;  // 0 .. BATCH*HW-1
    int b = pos / HW;
    int hw = pos - b * HW;
    const float* xb = x + (size_t)b * CDIM * HW + hw;
    size_t base = (size_t)b * CDIM * HW + hw;
    float s = 0.f, s2 = 0.f;
    #pragma unroll 8
    for (int c = 0; c < CDIM; c++) {
        float v = xb[(size_t)c * HW];
        s += v; s2 += v * v;
    }
    const float invC = 1.0f / CDIM;
    float mean = s * invC;
    float var  = s2 * invC - mean * mean;
    float r = rsqrtf(var + 1e-5f);
    #pragma unroll 8
    for (int c = 0; c < CDIM; c++) {
        float y = (xb[(size_t)c * HW] - mean) * r * g[c];
        split_bf16(y, g_xh[base + (size_t)c * HW], g_xl[base + (size_t)c * HW]);
    }
}

// ---------------- output channel layernorm (fp32 -> fp32) ------------------
__global__ void ln_out_kernel(const float* __restrict__ g,
                              float* __restrict__ out) {
    int pos = blockIdx.x * blockDim.x + threadIdx.x;
    int b = pos / HW;
    int hw = pos - b * HW;
    const float* xb = g_z + (size_t)b * CDIM * HW + hw;
    float* yb       = out + (size_t)b * CDIM * HW + hw;
    float s = 0.f, s2 = 0.f;
    #pragma unroll 8
    for (int c = 0; c < CDIM; c++) {
        float v = xb[(size_t)c * HW];
        s += v; s2 += v * v;
    }
    const float invC = 1.0f / CDIM;
    float mean = s * invC;
    float var  = s2 * invC - mean * mean;
    float r = rsqrtf(var + 1e-5f);
    #pragma unroll 8
    for (int c = 0; c < CDIM; c++) {
        yb[(size_t)c * HW] = (xb[(size_t)c * HW] - mean) * r * g[c];
    }
}

// ---------------- tensor-core GEMM (3-term bf16 split) ----------------------
// Y[b] = A[M,K] @ X[b][K,N], N = HW. CTA tile 128x128x32, 8 warps of 64x32.
__device__ __forceinline__ uint32_t sptr(const void* p) {
    return (uint32_t)__cvta_generic_to_shared(p);
}
__device__ __forceinline__ void cp_async16(void* sm, const void* gm) {
    asm volatile("cp.async.cg.shared.global [%0], [%1], 16;\n"
                 :: "r"(sptr(sm)), "l"(gm));
}
__device__ __forceinline__ void ldsm_x4(uint32_t* r, uint32_t a) {
    asm volatile("ldmatrix.sync.aligned.m8n8.x4.shared.b16 {%0,%1,%2,%3}, [%4];"
                 : "=r"(r[0]), "=r"(r[1]), "=r"(r[2]), "=r"(r[3]) : "r"(a));
}
__device__ __forceinline__ void ldsm_x2t(uint32_t* r, uint32_t a) {
    asm volatile("ldmatrix.sync.aligned.m8n8.x2.trans.shared.b16 {%0,%1}, [%2];"
                 : "=r"(r[0]), "=r"(r[1]) : "r"(a));
}
__device__ __forceinline__ void mma_bf16(float* c, const uint32_t* a, const uint32_t* b) {
    asm volatile("mma.sync.aligned.m16n8k16.row.col.f32.bf16.bf16.f32 "
                 "{%0,%1,%2,%3},{%4,%5,%6,%7},{%8,%9},{%0,%1,%2,%3};"
                 : "+f"(c[0]), "+f"(c[1]), "+f"(c[2]), "+f"(c[3])
                 : "r"(a[0]), "r"(a[1]), "r"(a[2]), "r"(a[3]), "r"(b[0]), "r"(b[1]));
}

// NOTE: pointers must be resolved in DEVICE code (device globals can't be
// passed as kernel args from host) — hence the __global__ wrappers below.
template<int M, int K>
__device__ __forceinline__ void mma_gemm_body(const __nv_bfloat16* __restrict__ Ah,
                                              const __nv_bfloat16* __restrict__ Al,
                                              const __nv_bfloat16* __restrict__ Xh,
                                              const __nv_bfloat16* __restrict__ Xl,
                                              float* __restrict__ Y) {
    constexpr int N = HW;
    constexpr int BM = 128, BN = 128, BK = 32;
    constexpr int AP = BK + 8;   // 40 halves/row (80B): 16B-aligned rows
    constexpr int BP = BN + 8;   // 136 halves/row (272B)
    constexpr int A_SZ = BM * AP;   // 5120 halves
    constexpr int B_SZ = BK * BP;   // 4352 halves
    constexpr int STAGE = 2 * A_SZ + 2 * B_SZ;
    extern __shared__ __nv_bfloat16 smem[];

    int b = blockIdx.z;
    const __nv_bfloat16* XhB = Xh + (size_t)b * K * N;
    const __nv_bfloat16* XlB = Xl + (size_t)b * K * N;
    float* Yb = Y + (size_t)b * M * N;
    int tm0 = blockIdx.y * BM;
    int tn0 = blockIdx.x * BN;
    int t = threadIdx.x;
    int lane = t & 31, warp = t >> 5;
    int wm = (warp & 1) * 64, wn = (warp >> 1) * 32;

    auto load_stage = [&](int kc, int s) {
        __nv_bfloat16* sa_h = smem + (size_t)s * STAGE;
        __nv_bfloat16* sa_l = sa_h + A_SZ;
        __nv_bfloat16* sb_h = sa_l + A_SZ;
        __nv_bfloat16* sb_l = sb_h + B_SZ;
        int k0 = kc * BK;
        #pragma unroll
        for (int i = 0; i < 2; i++) {
            int c = t + i * 256;
            int m  = c >> 2, kk = (c & 3) * 8;
            cp_async16(&sa_h[m * AP + kk], &Ah[(size_t)(tm0 + m) * K + k0 + kk]);
            cp_async16(&sa_l[m * AP + kk], &Al[(size_t)(tm0 + m) * K + k0 + kk]);
            int kr = c >> 4, nn = (c & 15) * 8;
            cp_async16(&sb_h[kr * BP + nn], &XhB[(size_t)(k0 + kr) * N + tn0 + nn]);
            cp_async16(&sb_l[kr * BP + nn], &XlB[(size_t)(k0 + kr) * N + tn0 + nn]);
        }
        asm volatile("cp.async.commit_group;");
    };

    float acc[4][4][4];
    #pragma unroll
    for (int i = 0; i < 4; i++)
        #pragma unroll
        for (int j = 0; j < 4; j++)
            #pragma unroll
            for (int r = 0; r < 4; r++) acc[i][j][r] = 0.f;

    load_stage(0, 0);
    constexpr int KC = K / BK;
    for (int kc = 0; kc < KC; kc++) {
        int s = kc & 1;
        asm volatile("cp.async.wait_group 0;");
        __syncthreads();
        if (kc + 1 < KC) load_stage(kc + 1, s ^ 1);

        __nv_bfloat16* sa_h = smem + (size_t)s * STAGE;
        __nv_bfloat16* sa_l = sa_h + A_SZ;
        __nv_bfloat16* sb_h = sa_l + A_SZ;
        __nv_bfloat16* sb_l = sb_h + B_SZ;

        #pragma unroll
        for (int ks = 0; ks < 2; ks++) {
            uint32_t bh[4][2], bl[4][2];
            int brow = ks * 16 + (lane & 15);
            #pragma unroll
            for (int nt = 0; nt < 4; nt++) {
                ldsm_x2t(bh[nt], sptr(&sb_h[brow * BP + wn + nt * 8]));
                ldsm_x2t(bl[nt], sptr(&sb_l[brow * BP + wn + nt * 8]));
            }
            uint32_t a[4][4];
            int arow = lane & 15;
            int acol = ks * 16 + (lane >> 4) * 8;
            #pragma unroll
            for (int mt = 0; mt < 4; mt++)
                ldsm_x4(a[mt], sptr(&sa_h[(wm + mt * 16 + arow) * AP + acol]));
            #pragma unroll
            for (int mt = 0; mt < 4; mt++)
                #pragma unroll
                for (int nt = 0; nt < 4; nt++) {
                    mma_bf16(acc[mt][nt], a[mt], bh[nt]);
                    mma_bf16(acc[mt][nt], a[mt], bl[nt]);
                }
            #pragma unroll
            for (int mt = 0; mt < 4; mt++)
                ldsm_x4(a[mt], sptr(&sa_l[(wm + mt * 16 + arow) * AP + acol]));
            #pragma unroll
            for (int mt = 0; mt < 4; mt++)
                #pragma unroll
                for (int nt = 0; nt < 4; nt++)
                    mma_bf16(acc[mt][nt], a[mt], bh[nt]);
        }
        __syncthreads();
    }

    #pragma unroll
    for (int mt = 0; mt < 4; mt++)
        #pragma unroll
        for (int nt = 0; nt < 4; nt++) {
            int m = tm0 + wm + mt * 16 + (lane >> 2);
            int n = tn0 + wn + nt * 8 + (lane & 3) * 2;
            *(float2*)&Yb[(size_t)m * N + n]       = make_float2(acc[mt][nt][0], acc[mt][nt][1]);
            *(float2*)&Yb[(size_t)(m + 8) * N + n] = make_float2(acc[mt][nt][2], acc[mt][nt][3]);
        }
}

// wrappers: device-global pointers resolved in device code
__global__ void __launch_bounds__(256) gemm_qkv_kernel() {
    mma_gemm_body<QKV, CDIM>(g_wh, g_wl, g_xh, g_xl, g_qkv1);
}
__global__ void __launch_bounds__(256) gemm_out_kernel() {
    mma_gemm_body<CDIM, INNER>(g_owh, g_owl, g_ah, g_al, g_z);
}

// ---------------- depthwise 3x3, smem-tiled ---------------------------------
__global__ void dwconv3_kernel(const float* __restrict__ qwd,
                               const float* __restrict__ kwd,
                               const float* __restrict__ vwd) {
    __shared__ float s[10][WW + 2];
    int bc = blockIdx.y;              // b*QKV + c
    int c = bc % QKV;
    const float* wp = (c < 256) ? (qwd + c * 9)
                    : (c < 512) ? (kwd + (c - 256) * 9)
                                : (vwd + (c - 512) * 9);
    float w0 = wp[0], w1 = wp[1], w2 = wp[2];
    float w3 = wp[3], w4 = wp[4], w5 = wp[5];
    float w6 = wp[6], w7 = wp[7], w8 = wp[8];
    const float* ip = g_qkv1 + (size_t)bc * HW;
    int h0 = blockIdx.x * 8;
    int tx = threadIdx.x;  // 0..95
    int ty = threadIdx.y;  // 0..7
    #pragma unroll
    for (int r = ty; r < 10; r += 8) {
        int h = h0 - 1 + r;
        s[r][tx + 1] = (h >= 0 && h < HH) ? ip[h * WW + tx] : 0.f;
        if (tx == 0) { s[r][0] = 0.f; s[r][WW + 1] = 0.f; }
    }
    __syncthreads();
    float acc = w0 * s[ty][tx]     + w1 * s[ty][tx + 1]     + w2 * s[ty][tx + 2]
              + w3 * s[ty + 1][tx] + w4 * s[ty + 1][tx + 1] + w5 * s[ty + 1][tx + 2]
              + w6 * s[ty + 2][tx] + w7 * s[ty + 2][tx + 1] + w8 * s[ty + 2][tx + 2];
    g_qkv2[(size_t)bc * HW + (h0 + ty) * WW + tx] = acc;
}

// ---------------- k softmax stats -------------------------------------------
__global__ void kstats_kernel() {
    int bc = blockIdx.x;            // 0 .. BATCH*INNER-1
    int b = bc / INNER, c = bc % INNER;
    const float* kp = g_qkv2 + ((size_t)b * QKV + INNER + c) * HW;
    int t = threadIdx.x;
    __shared__ float sm[256];
    float m = -1e30f;
    for (int i = t; i < HW; i += 256) m = fmaxf(m, kp[i]);
    sm[t] = m; __syncthreads();
    for (int s = 128; s > 0; s >>= 1) { if (t < s) sm[t] = fmaxf(sm[t], sm[t + s]); __syncthreads(); }
    m = sm[0];
    __syncthreads();
    float sum = 0.f;
    for (int i = t; i < HW; i += 256) sum += __expf(kp[i] - m);
    sm[t] = sum; __syncthreads();
    for (int s = 128; s > 0; s >>= 1) { if (t < s) sm[t] += sm[t + s]; __syncthreads(); }
    if (t == 0) { g_kmax[bc] = m; g_krsum[bc] = 1.0f / sm[0]; }
}

// ---------------- context = softmax_k^T @ v, partial over n-chunks ----------
__global__ void context_part_kernel() {
    int bh = blockIdx.x;
    int chunk = blockIdx.y;          // 0..8, 1024 positions each
    int b = bh / HEADS, h = bh % HEADS;
    const float* kp = g_qkv2 + ((size_t)b * QKV + INNER + h * DH) * HW;
    const float* vp = g_qkv2 + ((size_t)b * QKV + 2 * INNER + h * DH) * HW;
    const float* km = g_kmax  + b * INNER + h * DH;
    const float* kr = g_krsum + b * INNER + h * DH;
    __shared__ float sk[DH][33];
    __shared__ float sv[DH][33];
    int t = threadIdx.x;             // 256
    int e = t & 31;
    int d0 = (t >> 5) * 4;
    float acc0 = 0.f, acc1 = 0.f, acc2 = 0.f, acc3 = 0.f;
    int nbeg = chunk * 1024, nend = nbeg + 1024;
    for (int n0 = nbeg; n0 < nend; n0 += 32) {
        #pragma unroll
        for (int i = 0; i < 4; i++) {
            int idx = t + i * 256;
            int d = idx >> 5, nn = idx & 31;
            float kv = kp[(size_t)d * HW + n0 + nn];
            sk[d][nn] = __expf(kv - km[d]) * kr[d];
            sv[d][nn] = vp[(size_t)d * HW + n0 + nn];
        }
        __syncthreads();
        #pragma unroll
        for (int nn = 0; nn < 32; nn++) {
            float vv = sv[e][nn];
            acc0 += sk[d0 + 0][nn] * vv;
            acc1 += sk[d0 + 1][nn] * vv;
            acc2 += sk[d0 + 2][nn] * vv;
            acc3 += sk[d0 + 3][nn] * vv;
        }
        __syncthreads();
    }
    float* cp = g_ctxp + ((size_t)chunk * BATCH * HEADS + bh) * DH * DH;
    cp[(d0 + 0) * DH + e] = acc0;
    cp[(d0 + 1) * DH + e] = acc1;
    cp[(d0 + 2) * DH + e] = acc2;
    cp[(d0 + 3) * DH + e] = acc3;
}
__global__ void context_reduce_kernel() {
    int bh = blockIdx.x;
    int i = threadIdx.x;             // 1024
    float s = 0.f;
    #pragma unroll
    for (int c = 0; c < 9; c++)
        s += g_ctxp[((size_t)c * BATCH * HEADS + bh) * DH * DH + i];
    g_ctx[(size_t)bh * DH * DH + i] = s;
}

// ---------------- q softmax @ context + silu -> split bf16 ------------------
__global__ void qattn_kernel() {
    int bh = blockIdx.y;
    int b = bh / HEADS, h = bh % HEADS;
    int n = blockIdx.x * 256 + threadIdx.x;
    __shared__ float sctx[DH][DH];
    for (int i = threadIdx.x; i < DH * DH; i += 256)
        sctx[i / DH][i % DH] = g_ctx[(size_t)bh * DH * DH + i];
    __syncthreads();
    const float* qp = g_qkv2 + ((size_t)b * QKV + h * DH) * HW + n;
    float qv[DH];
    float m = -1e30f;
    #pragma unroll
    for (int d = 0; d < DH; d++) { qv[d] = qp[(size_t)d * HW]; m = fmaxf(m, qv[d]); }
    float sum = 0.f;
    #pragma unroll
    for (int d = 0; d < DH; d++) { qv[d] = __expf(qv[d] - m); sum += qv[d]; }
    float sc = 0.17677669529663688f / sum;  // (1/sqrt(32)) / sum
    #pragma unroll
    for (int d = 0; d < DH; d++) qv[d] *= sc;
    size_t obase = ((size_t)b * INNER + h * DH) * HW + n;
    #pragma unroll
    for (int e = 0; e < DH; e++) {
        float o = 0.f;
        #pragma unroll
        for (int d = 0; d < DH; d++) o += qv[d] * sctx[d][e];
        o = o / (1.0f + __expf(-o));   // silu
        split_bf16(o, g_ah[obase + (size_t)e * HW], g_al[obase + (size_t)e * HW]);
    }
}

// ---------------- launch ----------------------------------------------------
extern "C" void kernel_launch(void* const* d_in, const int* in_sizes, int n_in,
                              void* d_out, int out_size) {
    const float* fmap       = (const float*)d_in[0];
    const float* norm_g     = (const float*)d_in[1];
    const float* q_w1       = (const float*)d_in[2];
    const float* q_wd       = (const float*)d_in[3];
    const float* k_w1       = (const float*)d_in[4];
    const float* k_wd       = (const float*)d_in[5];
    const float* v_w1       = (const float*)d_in[6];
    const float* v_wd       = (const float*)d_in[7];
    const float* out_w      = (const float*)d_in[8];
    const float* out_norm_g = (const float*)d_in[9];
    float* out = (float*)d_out;

    // dynamic smem for GEMM: 2 stages * (2*128*40 + 2*32*136) halves * 2B
    const int SMEM_BYTES = 2 * (2 * 128 * 40 + 2 * 32 * 136) * 2;  // 75776
    cudaFuncSetAttribute(gemm_qkv_kernel,
                         cudaFuncAttributeMaxDynamicSharedMemorySize, SMEM_BYTES);
    cudaFuncSetAttribute(gemm_out_kernel,
                         cudaFuncAttributeMaxDynamicSharedMemorySize, SMEM_BYTES);

    // bf16-pair weights
    convert_qkvw_kernel<<<(INNER * CDIM) / 256, 256>>>(q_w1, k_w1, v_w1);
    convert_outw_kernel<<<(CDIM * INNER) / 256, 256>>>(out_w);

    // input LN -> split bf16 planes
    ln_in_kernel<<<(BATCH * HW) / 256, 256>>>(fmap, norm_g);

    // qkv = Wqkv @ xn  (tensor cores)
    gemm_qkv_kernel<<<dim3(HW / 128, QKV / 128, BATCH), 256, SMEM_BYTES>>>();

    // depthwise 3x3
    dwconv3_kernel<<<dim3(HH / 8, BATCH * QKV), dim3(96, 8)>>>(q_wd, k_wd, v_wd);

    // attention
    kstats_kernel<<<BATCH * INNER, 256>>>();
    context_part_kernel<<<dim3(BATCH * HEADS, 9), 256>>>();
    context_reduce_kernel<<<BATCH * HEADS, 1024>>>();
    qattn_kernel<<<dim3(HW / 256, BATCH * HEADS), 256>>>();

    // out projection (tensor cores)
    gemm_out_kernel<<<dim3(HW / 128, CDIM / 128, BATCH), 256, SMEM_BYTES>>>();

    // final LN
    ln_out_kernel<<<(BATCH * HW) / 256, 256>>>(out_norm_g, out);
}